// round 8
// baseline (speedup 1.0000x reference)
#include <cuda_runtime.h>

// ---------------------------------------------------------------------------
// MWDLSTMGCT: only the L->L wavelet path + LSTM3 are live (output = last time
// index of concat == s3 final h).
//   GEMM1: sig(x @ W1L^T + b1L) -> avgpool2 -> xl1 (256x512)
//   GEMM2: sig(xl1 @ W2L^T + b2L) -> avgpool2 -> xl2 (256x256)
//   LSTM3: T=256 steps, H=100, scalar input per step (software-pipelined)
//   out[b] = h_final[b] . Wout + bout
// ---------------------------------------------------------------------------

#define BATCH 256
#define HID   100
#define G4    400
#define T3    256

__device__ float g_xl1[BATCH * 512];
__device__ float g_xl2[BATCH * 256];

__device__ __forceinline__ float sigf(float x) {
    return 1.0f / (1.0f + __expf(-x));
}

__device__ __forceinline__ float tanh_fast(float x) {
    float xc = fminf(fmaxf(x, -15.0f), 15.0f);
    float e  = __expf(2.0f * xc);
    return __fdividef(e - 1.0f, e + 1.0f);
}

// packed f32x2 FMA (Blackwell; only reachable via PTX)
__device__ __forceinline__ unsigned long long fma2(unsigned long long a,
                                                   unsigned long long b,
                                                   unsigned long long c) {
    unsigned long long d;
    asm("fma.rn.f32x2 %0, %1, %2, %3;" : "=l"(d) : "l"(a), "l"(b), "l"(c));
    return d;
}

__device__ __forceinline__ float2 unpack2(unsigned long long a) {
    float2 r;
    asm("mov.b64 {%0, %1}, %2;" : "=f"(r.x), "=f"(r.y) : "l"(a));
    return r;
}

// ---------------------------------------------------------------------------
// out_pooled[M x N/2] = avgpool2( sigmoid( A[MxK] @ W[NxK]^T + bias[N] ) )
// BM=16, BN=64, BK=32, 128 threads, 2x4 micro-tile.
// Double-buffered smem + register prefetch: LDG for tile t+1 issued before
// the compute of tile t, so global latency is hidden under 32 k-iterations.
// ---------------------------------------------------------------------------
__global__ __launch_bounds__(128)
void gemm_sig_pool(const float* __restrict__ A, const float* __restrict__ W,
                   const float* __restrict__ bias, float* __restrict__ out,
                   int K, int N) {
    const int BM = 16, BN = 64, BK = 32;
    __shared__ float As[2][BM][BK + 1];
    __shared__ float Ws[2][BN][BK + 1];

    int tid = threadIdx.x;          // 0..127
    int tx = tid & 15;              // n group (4 cols)
    int ty = tid >> 4;              // m group (2 rows)
    int m0 = blockIdx.x * BM;
    int n0 = blockIdx.y * BN;
    int lk = tid & 31;              // k within tile
    int lr = tid >> 5;              // 0..3

    float acc[2][4];
#pragma unroll
    for (int i = 0; i < 2; i++)
#pragma unroll
        for (int j = 0; j < 4; j++) acc[i][j] = 0.0f;

    float pa[4], pw[16];

    // prefetch tile 0 -> regs -> smem buf 0
#pragma unroll
    for (int i = 0; i < 4; i++)  pa[i] = A[(m0 + lr + i * 4) * K + lk];
#pragma unroll
    for (int i = 0; i < 16; i++) pw[i] = W[(n0 + lr + i * 4) * K + lk];
#pragma unroll
    for (int i = 0; i < 4; i++)  As[0][lr + i * 4][lk] = pa[i];
#pragma unroll
    for (int i = 0; i < 16; i++) Ws[0][lr + i * 4][lk] = pw[i];

    int ntiles = K / BK;
    for (int t = 0; t < ntiles; t++) {
        __syncthreads();
        int cur = t & 1;

        if (t + 1 < ntiles) {                 // issue next-tile loads early
            int k0 = (t + 1) * BK + lk;
#pragma unroll
            for (int i = 0; i < 4; i++)  pa[i] = A[(m0 + lr + i * 4) * K + k0];
#pragma unroll
            for (int i = 0; i < 16; i++) pw[i] = W[(n0 + lr + i * 4) * K + k0];
        }

#pragma unroll
        for (int k = 0; k < BK; k++) {
            float a0 = As[cur][ty * 2][k];
            float a1 = As[cur][ty * 2 + 1][k];
            float w0 = Ws[cur][tx * 4 + 0][k];
            float w1 = Ws[cur][tx * 4 + 1][k];
            float w2 = Ws[cur][tx * 4 + 2][k];
            float w3 = Ws[cur][tx * 4 + 3][k];
            acc[0][0] += a0 * w0; acc[0][1] += a0 * w1;
            acc[0][2] += a0 * w2; acc[0][3] += a0 * w3;
            acc[1][0] += a1 * w0; acc[1][1] += a1 * w1;
            acc[1][2] += a1 * w2; acc[1][3] += a1 * w3;
        }

        if (t + 1 < ntiles) {                 // store into the other buffer
            int nx = (t + 1) & 1;
#pragma unroll
            for (int i = 0; i < 4; i++)  As[nx][lr + i * 4][lk] = pa[i];
#pragma unroll
            for (int i = 0; i < 16; i++) Ws[nx][lr + i * 4][lk] = pw[i];
        }
    }

    int halfN = N >> 1;
#pragma unroll
    for (int i = 0; i < 2; i++) {
        int m = m0 + ty * 2 + i;
#pragma unroll
        for (int j = 0; j < 2; j++) {
            int n = n0 + tx * 4 + j * 2;
            float v0 = sigf(acc[i][j * 2]     + bias[n]);
            float v1 = sigf(acc[i][j * 2 + 1] + bias[n + 1]);
            out[m * halfN + (n >> 1)] = 0.5f * (v0 + v1);
        }
    }
}

// ---------------------------------------------------------------------------
// LSTM3: 128 blocks x 2 batch elements, 512 threads (16 warps).
//   threads 0..399   : matvec engine, thread t owns Whh row t in 50 f32x2 regs
//   threads 416..511 : gate engine (96 threads; threads 416..419 take 2 units)
// Software pipeline per step s:
//   half 1: matvec zB(s)   || gates A(s)  (h_A(s) <- z_A(s))
//   half 2: matvec zA(s+1) || gates B(s)
// Gate latency (MUFU chains) hides entirely under the other element's matvec.
// ---------------------------------------------------------------------------
__global__ __launch_bounds__(512, 1)
void lstm_kernel(const float* __restrict__ xin,   // [BATCH, 256] = g_xl2
                 const float* __restrict__ Wih,   // [400,1]
                 const float* __restrict__ Whh,   // [400,100]
                 const float* __restrict__ b,     // [400]
                 const float* __restrict__ Wout,  // [1,100]
                 const float* __restrict__ bout,  // [1]
                 float* __restrict__ out) {       // [BATCH]
    __shared__ alignas(16) float hA[104];
    __shared__ alignas(16) float hB[104];
    __shared__ float zA[G4];
    __shared__ float zB[G4];
    __shared__ float xA[T3];
    __shared__ float xB[T3];
    __shared__ float red[200];

    int t  = threadIdx.x;
    int bA = blockIdx.x * 2;
    int bB = bA + 1;

    bool mv   = (t < G4);
    bool gate = (t >= 416);
    int  g    = t - 416;                 // 0..95
    int  g2   = (gate && g < 4) ? g + 96 : -1;

    // weight-stationary Whh row
    unsigned long long wp[50];
    float wih_t = 0.0f, b_t = 0.0f;
    if (mv) {
        const unsigned long long* wr =
            (const unsigned long long*)(Whh + t * HID);   // rows 400B, 16B aligned
#pragma unroll
        for (int k = 0; k < 50; k++) wp[k] = wr[k];
        wih_t = Wih[t];
        b_t   = b[t];
        zA[t] = fmaf(xin[bA * T3], wih_t, b_t);   // zA(0): h(-1)=0 (global x read)
    }
    for (int i = t; i < T3; i += 512) {
        xA[i] = xin[bA * T3 + i];
        xB[i] = xin[bB * T3 + i];
    }
    if (t < 104) { hA[t] = 0.0f; hB[t] = 0.0f; }

    float cA = 0.0f, cB = 0.0f, cA2 = 0.0f, cB2 = 0.0f;
    const ulonglong2* h2A = (const ulonglong2*)hA;
    const ulonglong2* h2B = (const ulonglong2*)hB;

    __syncthreads();

    for (int s = 0; s < T3; s++) {
        // ---- half 1: matvec zB(s)  ||  gates A(s) ----
        if (mv) {
            if (s == 0) {
                zB[t] = fmaf(xB[0], wih_t, b_t);
            } else {
                unsigned long long a0 = 0ull, a1 = 0ull;
#pragma unroll
                for (int k = 0; k < 25; k++) {
                    ulonglong2 h = h2B[k];
                    a0 = fma2(wp[2 * k],     h.x, a0);
                    a1 = fma2(wp[2 * k + 1], h.y, a1);
                }
                float2 f0 = unpack2(a0), f1 = unpack2(a1);
                zB[t] = (f0.x + f0.y) + (f1.x + f1.y) + fmaf(xB[s], wih_t, b_t);
            }
        } else if (gate) {
            float iv = sigf(zA[g]);
            float fv = sigf(zA[g + 100]);
            float gv = tanh_fast(zA[g + 200]);
            float ov = sigf(zA[g + 300]);
            cA = fv * cA + iv * gv;
            hA[g] = ov * tanh_fast(cA);
            if (g2 >= 0) {
                float iv2 = sigf(zA[g2]);
                float fv2 = sigf(zA[g2 + 100]);
                float gv2 = tanh_fast(zA[g2 + 200]);
                float ov2 = sigf(zA[g2 + 300]);
                cA2 = fv2 * cA2 + iv2 * gv2;
                hA[g2] = ov2 * tanh_fast(cA2);
            }
        }
        __syncthreads();   // zB(s), hA(s) published

        // ---- half 2: matvec zA(s+1)  ||  gates B(s) ----
        if (mv) {
            if (s < T3 - 1) {
                unsigned long long a0 = 0ull, a1 = 0ull;
#pragma unroll
                for (int k = 0; k < 25; k++) {
                    ulonglong2 h = h2A[k];
                    a0 = fma2(wp[2 * k],     h.x, a0);
                    a1 = fma2(wp[2 * k + 1], h.y, a1);
                }
                float2 f0 = unpack2(a0), f1 = unpack2(a1);
                zA[t] = (f0.x + f0.y) + (f1.x + f1.y) + fmaf(xA[s + 1], wih_t, b_t);
            }
        } else if (gate) {
            float iv = sigf(zB[g]);
            float fv = sigf(zB[g + 100]);
            float gv = tanh_fast(zB[g + 200]);
            float ov = sigf(zB[g + 300]);
            cB = fv * cB + iv * gv;
            hB[g] = ov * tanh_fast(cB);
            if (g2 >= 0) {
                float iv2 = sigf(zB[g2]);
                float fv2 = sigf(zB[g2 + 100]);
                float gv2 = tanh_fast(zB[g2 + 200]);
                float ov2 = sigf(zB[g2 + 300]);
                cB2 = fv2 * cB2 + iv2 * gv2;
                hB[g2] = ov2 * tanh_fast(cB2);
            }
        }
        __syncthreads();   // zA(s+1), hB(s) published
    }

    // ---- output projection: out[b] = dot(h(255), Wout) + bout ----
    if (t < HID) {
        red[t] = hA[t] * Wout[t];
    } else if (t >= 128 && t < 128 + HID) {
        red[t - 128 + HID] = hB[t - 128] * Wout[t - 128];
    }
    __syncthreads();
    if (t == 0) {
        float s1 = 0.0f;
        for (int j = 0; j < HID; j++) s1 += red[j];
        out[bA] = s1 + bout[0];
    } else if (t == 128) {
        float s2 = 0.0f;
        for (int j = 0; j < HID; j++) s2 += red[j + HID];
        out[bB] = s2 + bout[0];
    }
}

// ---------------------------------------------------------------------------
extern "C" void kernel_launch(void* const* d_in, const int* in_sizes, int n_in,
                              void* d_out, int out_size) {
    const float* x    = (const float*)d_in[0];
    const float* W1L  = (const float*)d_in[3];
    const float* b1L  = (const float*)d_in[4];
    const float* W2L  = (const float*)d_in[7];
    const float* b2L  = (const float*)d_in[8];
    const float* Wih3 = (const float*)d_in[15];
    const float* Whh3 = (const float*)d_in[16];
    const float* b3   = (const float*)d_in[17];
    const float* Wout = (const float*)d_in[18];
    const float* bout = (const float*)d_in[19];
    float* out = (float*)d_out;

    float* xl1;
    float* xl2;
    cudaGetSymbolAddress((void**)&xl1, g_xl1);
    cudaGetSymbolAddress((void**)&xl2, g_xl2);

    // Layer 1: x(256x1024) @ W1L^T -> sig -> pool -> xl1(256x512)
    gemm_sig_pool<<<dim3(256 / 16, 1024 / 64), 128>>>(x, W1L, b1L, xl1, 1024, 1024);
    // Layer 2: xl1(256x512) @ W2L^T -> sig -> pool -> xl2(256x256)
    gemm_sig_pool<<<dim3(256 / 16, 512 / 64), 128>>>(xl1, W2L, b2L, xl2, 512, 512);
    // LSTM3 + output projection
    lstm_kernel<<<BATCH / 2, 512>>>(xl2, Wih3, Whh3, b3, Wout, bout, out);
}

// round 9
// speedup vs baseline: 1.2604x; 1.2604x over previous
#include <cuda_runtime.h>

// ---------------------------------------------------------------------------
// MWDLSTMGCT: only the L->L wavelet path + LSTM3 are live (output = last time
// index of concat == s3 final h).
//   GEMM1: sig(x @ W1L^T + b1L) -> avgpool2 -> xl1 (256x512)
//   GEMM2: sig(xl1 @ W2L^T + b2L) -> avgpool2 -> xl2 (256x256)
//   LSTM3: T=256 steps, H=100, scalar input per step
//   out[b] = h_final[b] . Wout + bout
// ---------------------------------------------------------------------------

#define BATCH 256
#define HID   100
#define G4    400
#define T3    256

__device__ float g_xl1[BATCH * 512];
__device__ float g_xl2[BATCH * 256];

__device__ __forceinline__ float sigf(float x) {
    return 1.0f / (1.0f + __expf(-x));
}

__device__ __forceinline__ float tanh_fast(float x) {
    float xc = fminf(fmaxf(x, -15.0f), 15.0f);
    float e  = __expf(2.0f * xc);
    return __fdividef(e - 1.0f, e + 1.0f);
}

// packed f32x2 FMA (Blackwell; only reachable via PTX)
__device__ __forceinline__ unsigned long long fma2(unsigned long long a,
                                                   unsigned long long b,
                                                   unsigned long long c) {
    unsigned long long d;
    asm("fma.rn.f32x2 %0, %1, %2, %3;" : "=l"(d) : "l"(a), "l"(b), "l"(c));
    return d;
}

__device__ __forceinline__ float2 unpack2(unsigned long long a) {
    float2 r;
    asm("mov.b64 {%0, %1}, %2;" : "=f"(r.x), "=f"(r.y) : "l"(a));
    return r;
}

// ---------------------------------------------------------------------------
// out_pooled[M x N/2] = avgpool2( sigmoid( A[MxK] @ W[NxK]^T + bias[N] ) )
// BM=32, BN=64, BK=16, 128 threads, 4x4 micro-tile.
// Smem k-major: As[k][m], Ws[k][n] so operand fetch is 2x LDS.128 per k
// against 16 FFMA. Double-buffered, register-prefetched global loads.
// ---------------------------------------------------------------------------
#define GBM 32
#define GBN 64
#define GBK 16
#define APAD 36   // row stride for As (floats): keeps float4 alignment, no conflicts
#define WPAD 68   // row stride for Ws

__global__ __launch_bounds__(128)
void gemm_sig_pool(const float* __restrict__ A, const float* __restrict__ W,
                   const float* __restrict__ bias, float* __restrict__ out,
                   int K, int N) {
    __shared__ float As[2][GBK * APAD];
    __shared__ float Ws[2][GBK * WPAD];

    int tid = threadIdx.x;          // 0..127
    int tx = tid & 15;              // n group: cols tx*4..+3
    int ty = tid >> 4;              // m group: rows ty*4..+3
    int m0 = blockIdx.x * GBM;
    int n0 = blockIdx.y * GBN;

    // global-load assignment: each thread loads 1 float4 of A, 2 float4 of W
    int lr = tid >> 2;              // 0..31
    int lq = (tid & 3) * 4;         // k offset within tile {0,4,8,12}

    const float* Ag = A + (m0 + lr) * K + lq;        // row m0+lr
    const float* Wg0 = W + (n0 + lr) * K + lq;       // rows n0+lr, n0+lr+32
    const float* Wg1 = W + (n0 + lr + 32) * K + lq;

    float4 pa, pw0, pw1;
    pa  = *(const float4*)Ag;
    pw0 = *(const float4*)Wg0;
    pw1 = *(const float4*)Wg1;

    // scatter tile 0 into buffer 0 (k-major)
    {
        float* as = &As[0][0];
        float* ws = &Ws[0][0];
        as[(lq + 0) * APAD + lr] = pa.x;
        as[(lq + 1) * APAD + lr] = pa.y;
        as[(lq + 2) * APAD + lr] = pa.z;
        as[(lq + 3) * APAD + lr] = pa.w;
        ws[(lq + 0) * WPAD + lr] = pw0.x;
        ws[(lq + 1) * WPAD + lr] = pw0.y;
        ws[(lq + 2) * WPAD + lr] = pw0.z;
        ws[(lq + 3) * WPAD + lr] = pw0.w;
        ws[(lq + 0) * WPAD + lr + 32] = pw1.x;
        ws[(lq + 1) * WPAD + lr + 32] = pw1.y;
        ws[(lq + 2) * WPAD + lr + 32] = pw1.z;
        ws[(lq + 3) * WPAD + lr + 32] = pw1.w;
    }

    float acc[4][4];
#pragma unroll
    for (int i = 0; i < 4; i++)
#pragma unroll
        for (int j = 0; j < 4; j++) acc[i][j] = 0.0f;

    int ntiles = K / GBK;
    for (int t = 0; t < ntiles; t++) {
        __syncthreads();
        int cur = t & 1;

        if (t + 1 < ntiles) {                 // prefetch next tile into regs
            int ko = (t + 1) * GBK;
            pa  = *(const float4*)(Ag + ko);
            pw0 = *(const float4*)(Wg0 + ko);
            pw1 = *(const float4*)(Wg1 + ko);
        }

        const float* as = &As[cur][0];
        const float* ws = &Ws[cur][0];
#pragma unroll
        for (int k = 0; k < GBK; k++) {
            float4 a = *(const float4*)(as + k * APAD + ty * 4);
            float4 w = *(const float4*)(ws + k * WPAD + tx * 4);
            acc[0][0] += a.x * w.x; acc[0][1] += a.x * w.y;
            acc[0][2] += a.x * w.z; acc[0][3] += a.x * w.w;
            acc[1][0] += a.y * w.x; acc[1][1] += a.y * w.y;
            acc[1][2] += a.y * w.z; acc[1][3] += a.y * w.w;
            acc[2][0] += a.z * w.x; acc[2][1] += a.z * w.y;
            acc[2][2] += a.z * w.z; acc[2][3] += a.z * w.w;
            acc[3][0] += a.w * w.x; acc[3][1] += a.w * w.y;
            acc[3][2] += a.w * w.z; acc[3][3] += a.w * w.w;
        }

        if (t + 1 < ntiles) {                 // store prefetched tile
            int nx = (t + 1) & 1;
            float* asn = &As[nx][0];
            float* wsn = &Ws[nx][0];
            asn[(lq + 0) * APAD + lr] = pa.x;
            asn[(lq + 1) * APAD + lr] = pa.y;
            asn[(lq + 2) * APAD + lr] = pa.z;
            asn[(lq + 3) * APAD + lr] = pa.w;
            wsn[(lq + 0) * WPAD + lr] = pw0.x;
            wsn[(lq + 1) * WPAD + lr] = pw0.y;
            wsn[(lq + 2) * WPAD + lr] = pw0.z;
            wsn[(lq + 3) * WPAD + lr] = pw0.w;
            wsn[(lq + 0) * WPAD + lr + 32] = pw1.x;
            wsn[(lq + 1) * WPAD + lr + 32] = pw1.y;
            wsn[(lq + 2) * WPAD + lr + 32] = pw1.z;
            wsn[(lq + 3) * WPAD + lr + 32] = pw1.w;
        }
    }

    int halfN = N >> 1;
#pragma unroll
    for (int i = 0; i < 4; i++) {
        int m = m0 + ty * 4 + i;
#pragma unroll
        for (int j = 0; j < 2; j++) {
            int n = n0 + tx * 4 + j * 2;
            float v0 = sigf(acc[i][j * 2]     + bias[n]);
            float v1 = sigf(acc[i][j * 2 + 1] + bias[n + 1]);
            out[m * halfN + (n >> 1)] = 0.5f * (v0 + v1);
        }
    }
}

// ---------------------------------------------------------------------------
// LSTM3 (R6 structure): 128 blocks x 2 batch elements, 416 threads (13 warps).
// Thread t < 400 owns gate-unit t for BOTH elems: Whh row t in 50 packed
// f32x2 registers, h read via LDS.128 (25 per elem per step).
// Gate phase: elem A on threads 0..99, elem B on threads 128..227 -> the two
// nonlinearity chains run in parallel warps.
// ---------------------------------------------------------------------------
__global__ __launch_bounds__(416, 1)
void lstm_kernel(const float* __restrict__ xin,   // [BATCH, 256] = g_xl2
                 const float* __restrict__ Wih,   // [400,1]
                 const float* __restrict__ Whh,   // [400,100]
                 const float* __restrict__ b,     // [400]
                 const float* __restrict__ Wout,  // [1,100]
                 const float* __restrict__ bout,  // [1]
                 float* __restrict__ out) {       // [BATCH]
    __shared__ alignas(16) float hA[104];
    __shared__ alignas(16) float hB[104];
    __shared__ float zA[G4];
    __shared__ float zB[G4];
    __shared__ float xA[T3];
    __shared__ float xB[T3];
    __shared__ float red[228];

    int t  = threadIdx.x;
    int bA = blockIdx.x * 2;
    int bB = bA + 1;

    // preload per-element input sequences
    for (int i = t; i < T3; i += 416) {
        xA[i] = xin[bA * T3 + i];
        xB[i] = xin[bB * T3 + i];
    }
    if (t < 104) { hA[t] = 0.0f; hB[t] = 0.0f; }

    // weight-stationary: Whh row t in registers (packed pairs)
    unsigned long long wp[50];
    float wih_t = 0.0f, b_t = 0.0f;
    if (t < G4) {
        const unsigned long long* wr =
            (const unsigned long long*)(Whh + t * HID);   // rows 400B, 16B aligned
#pragma unroll
        for (int k = 0; k < 50; k++) wp[k] = wr[k];
        wih_t = Wih[t];
        b_t   = b[t];
    }

    float c = 0.0f;                          // cA for t<100, cB for t in [128,228)
    int tb = t - 128;
    const ulonglong2* h128A = (const ulonglong2*)hA;
    const ulonglong2* h128B = (const ulonglong2*)hB;

    for (int s = 0; s < T3; s++) {
        __syncthreads();          // h ready for this step
        if (t < G4) {
            unsigned long long a0 = 0ull, a1 = 0ull, d0 = 0ull, d1 = 0ull;
#pragma unroll
            for (int k = 0; k < 25; k++) {
                ulonglong2 ha = h128A[k];
                ulonglong2 hb = h128B[k];
                a0 = fma2(wp[2 * k],     ha.x, a0);
                a1 = fma2(wp[2 * k + 1], ha.y, a1);
                d0 = fma2(wp[2 * k],     hb.x, d0);
                d1 = fma2(wp[2 * k + 1], hb.y, d1);
            }
            float gbase  = fmaf(xA[s], wih_t, b_t);
            float gbaseB = fmaf(xB[s], wih_t, b_t);
            float2 fa0 = unpack2(a0), fa1 = unpack2(a1);
            float2 fb0 = unpack2(d0), fb1 = unpack2(d1);
            zA[t] = (fa0.x + fa0.y) + (fa1.x + fa1.y) + gbase;
            zB[t] = (fb0.x + fb0.y) + (fb1.x + fb1.y) + gbaseB;
        }
        __syncthreads();          // z complete
        if (t < HID) {
            float iv = sigf(zA[t]);
            float fv = sigf(zA[t + 100]);
            float gv = tanh_fast(zA[t + 200]);
            float ov = sigf(zA[t + 300]);
            c = fv * c + iv * gv;
            hA[t] = ov * tanh_fast(c);
        } else if (tb >= 0 && tb < HID) {
            float iv = sigf(zB[tb]);
            float fv = sigf(zB[tb + 100]);
            float gv = tanh_fast(zB[tb + 200]);
            float ov = sigf(zB[tb + 300]);
            c = fv * c + iv * gv;
            hB[tb] = ov * tanh_fast(c);
        }
    }

    __syncthreads();
    if (t < HID) {
        red[t] = hA[t] * Wout[t];
    } else if (tb >= 0 && tb < HID) {
        red[tb + 114] = hB[tb] * Wout[tb];
    }
    __syncthreads();
    if (t == 0) {
        float s1 = 0.0f;
        for (int j = 0; j < HID; j++) s1 += red[j];
        out[bA] = s1 + bout[0];
    } else if (t == 128) {
        float s2 = 0.0f;
        for (int j = 0; j < HID; j++) s2 += red[j + 114];
        out[bB] = s2 + bout[0];
    }
}

// ---------------------------------------------------------------------------
extern "C" void kernel_launch(void* const* d_in, const int* in_sizes, int n_in,
                              void* d_out, int out_size) {
    const float* x    = (const float*)d_in[0];
    const float* W1L  = (const float*)d_in[3];
    const float* b1L  = (const float*)d_in[4];
    const float* W2L  = (const float*)d_in[7];
    const float* b2L  = (const float*)d_in[8];
    const float* Wih3 = (const float*)d_in[15];
    const float* Whh3 = (const float*)d_in[16];
    const float* b3   = (const float*)d_in[17];
    const float* Wout = (const float*)d_in[18];
    const float* bout = (const float*)d_in[19];
    float* out = (float*)d_out;

    float* xl1;
    float* xl2;
    cudaGetSymbolAddress((void**)&xl1, g_xl1);
    cudaGetSymbolAddress((void**)&xl2, g_xl2);

    // Layer 1: x(256x1024) @ W1L^T -> sig -> pool -> xl1(256x512)
    gemm_sig_pool<<<dim3(256 / GBM, 1024 / GBN), 128>>>(x, W1L, b1L, xl1, 1024, 1024);
    // Layer 2: xl1(256x512) @ W2L^T -> sig -> pool -> xl2(256x256)
    gemm_sig_pool<<<dim3(256 / GBM, 512 / GBN), 128>>>(xl1, W2L, b2L, xl2, 512, 512);
    // LSTM3 + output projection
    lstm_kernel<<<BATCH / 2, 416>>>(xl2, Wih3, Whh3, b3, Wout, bout, out);
}